// round 10
// baseline (speedup 1.0000x reference)
#include <cuda_runtime.h>
#include <math.h>

#define Hh 160
#define Ww 480
#define HW 76800
#define NP 120000

typedef unsigned long long u64;

// ---------------- f32x2 packed helpers ----------------
__device__ __forceinline__ u64 pkdup(float x) {
    u64 r; asm("mov.b64 %0, {%1,%1};" : "=l"(r) : "f"(x)); return r;
}
__device__ __forceinline__ u64 f2fma(u64 a, u64 b, u64 c) {
    u64 d; asm("fma.rn.f32x2 %0, %1, %2, %3;" : "=l"(d) : "l"(a), "l"(b), "l"(c)); return d;
}
__device__ __forceinline__ u64 f2add(u64 a, u64 b) {
    u64 d; asm("add.rn.f32x2 %0, %1, %2;" : "=l"(d) : "l"(a), "l"(b)); return d;
}
__device__ __forceinline__ float hsum(u64 a) {
    float x, y; asm("mov.b64 {%0,%1}, %2;" : "=f"(x), "=f"(y) : "l"(a)); return x + y;
}
__device__ __forceinline__ float2 unpk(u64 a) {
    float x, y; asm("mov.b64 {%0,%1}, %2;" : "=f"(x), "=f"(y) : "l"(a));
    return make_float2(x, y);
}

// ---------------- scratch (no allocations allowed) ----------------
__device__ __align__(16) int    d_win[3][HW];
__device__ __align__(16) float4 d_G0[9][16];    // folded red_w0 -> tap weights [k][c/4]
__device__ __align__(16) float4 d_G1[9][32];    // folded red_w1 -> tap weights
__device__ __align__(16) float4 d_Wpt[9][64];   // sb_w[256:512] transposed to [k][o/4]
__device__ __align__(16) u64    d_Wb2[2560];    // img weights dup'd {w,w}, [c][10]
__device__ float  d_cb[9];                      // folded bias constants per tap
__device__ __align__(16) float  d_tp[9][HW];    // merged tap maps (REDG-accumulated)

// ---------------- K0: prep (blocks 0..8) + init (blocks 9..683) --------------
__global__ void k_initprep(const float* __restrict__ rw0, const float* __restrict__ rb0,
                           const float* __restrict__ rw1, const float* __restrict__ rb1,
                           const float* __restrict__ sbw) {
    int b = blockIdx.x;
    int tid = threadIdx.x;
    if (b < 9) {
        int k = b;
        d_Wb2[tid * 10 + k] = pkdup(sbw[tid * 9 + k]);             // img weights dup'd
        ((float*)d_Wpt)[k * 256 + tid] = sbw[(256 + tid) * 9 + k];
        if (tid < 64) {
            float s = 0.f;
            for (int o = 0; o < 256; o++) s += rw0[o * 64 + tid] * sbw[(256 + o) * 9 + k];
            ((float*)d_G0)[k * 64 + tid] = s;
        }
        if (tid < 128) {
            float s = 0.f;
            for (int o = 0; o < 256; o++) s += rw1[o * 128 + tid] * sbw[(256 + o) * 9 + k];
            ((float*)d_G1)[k * 128 + tid] = s;
        }
        if (tid == 0) {
            float s = 0.f;
            for (int o = 0; o < 256; o++) s += (rb0[o] + rb1[o]) * sbw[(256 + o) * 9 + k];
            d_cb[k] = s;
        }
    } else {
        int i = (b - 9) * 256 + tid;          // 0 .. 172799 float4 over d_tp
        ((float4*)d_tp)[i] = make_float4(0.f, 0.f, 0.f, 0.f);
        if (i < 3 * HW / 4) ((int4*)d_win)[i] = make_int4(-1, -1, -1, -1);
    }
}

// ---------------- K1: scatter, last-write-wins == max point index ------------
__global__ void k_scatter(const int* __restrict__ g0, const int* __restrict__ g1,
                          const int* __restrict__ g2) {
    int i = blockIdx.x * blockDim.x + threadIdx.x;
    if (i >= 3 * NP) return;
    int lvl = i / NP;
    int p = i - lvl * NP;
    const int* g = (lvl == 0) ? g0 : ((lvl == 1) ? g1 : g2);
    int2 xy = ((const int2*)g)[p];
    if (xy.x >= 0 && xy.x < Ww && xy.y >= 0 && xy.y < Hh)
        atomicMax(&d_win[lvl][xy.y * Ww + xy.x], p);
}

// ---------------- img part: quad-major loads, f32x2 math, REDG ----------------
// thread = 1 pixel-quad x 1/4 channels; LDG.128 data, dup'd-{w,w} smem weights
__device__ __forceinline__ void img_body(const float* __restrict__ img,
                                         const float* __restrict__ seg,
                                         u64* swb, int blk) {
    int tid = threadIdx.x;
    for (int i = tid; i < 1280; i += 256) ((ulonglong2*)swb)[i] = ((const ulonglong2*)d_Wb2)[i];
    __syncthreads();

    int cs = tid & 3;          // channel lane (0..3)
    int qi = tid >> 2;         // quad (0..63)
    int px = blk * 256 + qi * 4;

    u64 accE[9], accO[9];      // {p0,p1} and {p2,p3} sums per tap
#pragma unroll
    for (int k = 0; k < 9; k++) { accE[k] = 0ull; accO[k] = 0ull; }

#pragma unroll 4
    for (int m = 0; m < 64; m++) {
        int c = cs + 4 * m;
        ulonglong2 v = *(const ulonglong2*)(img + (size_t)c * HW + px);
        const u64* wp = swb + c * 10;
        ulonglong2 w01 = *(const ulonglong2*)(wp);
        ulonglong2 w23 = *(const ulonglong2*)(wp + 2);
        ulonglong2 w45 = *(const ulonglong2*)(wp + 4);
        ulonglong2 w67 = *(const ulonglong2*)(wp + 6);
        u64 w8 = wp[8];
        accE[0] = f2fma(v.x, w01.x, accE[0]); accO[0] = f2fma(v.y, w01.x, accO[0]);
        accE[1] = f2fma(v.x, w01.y, accE[1]); accO[1] = f2fma(v.y, w01.y, accO[1]);
        accE[2] = f2fma(v.x, w23.x, accE[2]); accO[2] = f2fma(v.y, w23.x, accO[2]);
        accE[3] = f2fma(v.x, w23.y, accE[3]); accO[3] = f2fma(v.y, w23.y, accO[3]);
        accE[4] = f2fma(v.x, w45.x, accE[4]); accO[4] = f2fma(v.y, w45.x, accO[4]);
        accE[5] = f2fma(v.x, w45.y, accE[5]); accO[5] = f2fma(v.y, w45.y, accO[5]);
        accE[6] = f2fma(v.x, w67.x, accE[6]); accO[6] = f2fma(v.y, w67.x, accO[6]);
        accE[7] = f2fma(v.x, w67.y, accE[7]); accO[7] = f2fma(v.y, w67.y, accO[7]);
        accE[8] = f2fma(v.x, w8,    accE[8]); accO[8] = f2fma(v.y, w8,    accO[8]);
    }

    // reduce over the 4 channel-lanes (packed adds)
#pragma unroll
    for (int k = 0; k < 9; k++) {
        accE[k] = f2add(accE[k], __shfl_xor_sync(0xffffffffu, accE[k], 1));
        accO[k] = f2add(accO[k], __shfl_xor_sync(0xffffffffu, accO[k], 1));
        accE[k] = f2add(accE[k], __shfl_xor_sync(0xffffffffu, accE[k], 2));
        accO[k] = f2add(accO[k], __shfl_xor_sync(0xffffffffu, accO[k], 2));
    }
    if (cs == 0) {
        float4 sg = *(const float4*)(seg + HW + px);
#pragma unroll
        for (int k = 0; k < 9; k++) {
            float2 e = unpk(accE[k]);
            float2 o = unpk(accO[k]);
            atomicAdd(&d_tp[k][px + 0], sg.x * e.x);
            atomicAdd(&d_tp[k][px + 1], sg.y * e.y);
            atomicAdd(&d_tp[k][px + 2], sg.z * o.x);
            atomicAdd(&d_tp[k][px + 3], sg.w * o.y);
        }
    }
}

// ---------------- voxel part: in-smem compaction, f32x2 gather, REDG ----------
// warp = 4 point-slots x 8 channel-lanes (1 point per slot per pass)
template <int LVL, int C4>
__device__ __forceinline__ void voxel_body(const float* __restrict__ vf,
                                           ulonglong2* sw, int2* s_lst, int* s_w,
                                           int blk) {
    int tid = threadIdx.x;
    const ulonglong2* wsrc = (LVL == 0) ? (const ulonglong2*)d_G0
                            : (LVL == 1) ? (const ulonglong2*)d_G1
                                         : (const ulonglong2*)d_Wpt;
    for (int i = tid; i < 9 * C4; i += 256) sw[i] = wsrc[i];

    // compact this block's 256 cells
    int cell = blk * 256 + tid;
    int p = d_win[LVL][cell];
    bool valid = p >= 0;
    unsigned m = __ballot_sync(0xffffffffu, valid);
    int lane = tid & 31;
    int w    = tid >> 5;
    if (lane == 0) s_w[w] = __popc(m);
    __syncthreads();
    if (tid == 0) {
        int t = 0;
#pragma unroll
        for (int i = 0; i < 8; i++) { int c = s_w[i]; s_w[i] = t; t += c; }
        s_w[8] = t;
    }
    __syncthreads();
    if (valid) {
        int pos = s_w[w] + __popc(m & ((1u << lane) - 1));
        s_lst[pos] = make_int2(cell, p);
    }
    __syncthreads();
    int n = s_w[8];

    int sub = lane >> 3;   // point slot (0..3)
    int cs  = lane & 7;    // channel lane (0..7)

    for (int base = 0; base < n; base += 32) {
        int i0 = base + w * 4 + sub;
        bool ok = i0 < n;
        int2 e = ok ? s_lst[i0] : make_int2(0, 0);
        const ulonglong2* row = (const ulonglong2*)vf + (size_t)e.y * C4;

        u64 acc[9];
#pragma unroll
        for (int k = 0; k < 9; k++) acc[k] = 0ull;

#pragma unroll 2
        for (int mm = 0; mm < C4 / 8; mm++) {
            int c4 = cs + 8 * mm;
            ulonglong2 v = row[c4];
#pragma unroll
            for (int k = 0; k < 9; k++) {
                ulonglong2 wv = sw[k * C4 + c4];
                acc[k] = f2fma(v.x, wv.x, acc[k]);
                acc[k] = f2fma(v.y, wv.y, acc[k]);
            }
        }
#pragma unroll
        for (int k = 0; k < 9; k++) {
            float s = hsum(acc[k]);
            s += __shfl_xor_sync(0xffffffffu, s, 1);
            s += __shfl_xor_sync(0xffffffffu, s, 2);
            s += __shfl_xor_sync(0xffffffffu, s, 4);
            if (cs == 0 && ok) atomicAdd(&d_tp[k][e.x], s);   // REDG.F32 no-return
        }
    }
}

// ---------------- K2: merged work kernel, interleaved block types -------------
// 1200 blocks: b&3 -> {lvl2, lvl1, lvl0, img}, each 300 blocks of 256 cells/px
__global__ void __launch_bounds__(256, 4) k_work(const float* __restrict__ img,
                                                 const float* __restrict__ seg,
                                                 const float* __restrict__ vf0,
                                                 const float* __restrict__ vf1,
                                                 const float* __restrict__ vf2) {
    __shared__ __align__(16) u64 swb[2560];   // 20KB: img dup weights / voxel weights
    __shared__ __align__(16) int2 s_lst[256];
    __shared__ int s_w[9];
    int b = blockIdx.x;
    int type = b & 3;
    int sb = b >> 2;
    if (type == 0)      voxel_body<2, 64>(vf2, (ulonglong2*)swb, s_lst, s_w, sb);
    else if (type == 1) voxel_body<1, 32>(vf1, (ulonglong2*)swb, s_lst, s_w, sb);
    else if (type == 2) voxel_body<0, 16>(vf0, (ulonglong2*)swb, s_lst, s_w, sb);
    else                img_body(img, seg, swb, sb);
}

// ---------------- K3: att (into smem) + gated output stream -------------------
__global__ void __launch_bounds__(256) k_attout(const float* __restrict__ img,
                                                const float* __restrict__ seg,
                                                const float* __restrict__ sbb,
                                                float* __restrict__ out) {
    __shared__ __align__(16) float satt[256];
    __shared__ float scb[9];
    int tid = threadIdx.x;
    int base = blockIdx.x * 256;
    if (tid < 9) scb[tid] = d_cb[tid];
    __syncthreads();
    {
        int pix = base + tid;
        int y = pix / Ww;
        int x = pix - y * Ww;
        float sum = sbb[0];
#pragma unroll
        for (int ky = 0; ky < 3; ky++) {
            int yy = y + ky - 1;
            if (yy < 0 || yy >= Hh) continue;
#pragma unroll
            for (int kx = 0; kx < 3; kx++) {
                int xx = x + kx - 1;
                if (xx < 0 || xx >= Ww) continue;
                int kk = ky * 3 + kx;
                sum += d_tp[kk][yy * Ww + xx] + scb[kk];
            }
        }
        float att = 1.f / (1.f + expf(-sum));
        satt[tid] = att * seg[HW + pix];
    }
    __syncthreads();

    // stream all 256 channels for this block's 256 pixels (64 float4 per channel)
    int q = tid & 63;          // pixel-quad within block
    int c0 = tid >> 6;         // starting channel (0..3)
    float4 a = ((const float4*)satt)[q];
    const float4* im4 = (const float4*)img;
    float4* o4 = (float4*)out;
    size_t idx = (size_t)c0 * (HW / 4) + (base / 4) + q;
#pragma unroll 8
    for (int c = c0; c < 256; c += 4, idx += (size_t)4 * (HW / 4)) {
        float4 v = im4[idx];
        v.x *= a.x; v.y *= a.y; v.z *= a.z; v.w *= a.w;
        o4[idx] = v;
    }
}

extern "C" void kernel_launch(void* const* d_in, const int* in_sizes, int n_in,
                              void* d_out, int out_size) {
    const float* img = (const float*)d_in[0];
    const float* seg = (const float*)d_in[1];

    int iv0, iv1, iv2, ig0, ig1, ig2;
    if (in_sizes[3] == 2 * NP) { iv0 = 2; ig0 = 3; iv1 = 4; ig1 = 5; iv2 = 6; ig2 = 7; }
    else                       { iv0 = 2; iv1 = 3; iv2 = 4; ig0 = 5; ig1 = 6; ig2 = 7; }

    const float* vf0 = (const float*)d_in[iv0];
    const float* vf1 = (const float*)d_in[iv1];
    const float* vf2 = (const float*)d_in[iv2];
    const int*   g0  = (const int*)d_in[ig0];
    const int*   g1  = (const int*)d_in[ig1];
    const int*   g2  = (const int*)d_in[ig2];
    const float* rw0 = (const float*)d_in[8];
    const float* rb0 = (const float*)d_in[9];
    const float* rw1 = (const float*)d_in[10];
    const float* rb1 = (const float*)d_in[11];
    const float* sbw = (const float*)d_in[12];
    const float* sbb = (const float*)d_in[13];

    k_initprep<<<684, 256>>>(rw0, rb0, rw1, rb1, sbw);
    k_scatter<<<(3 * NP + 255) / 256, 256>>>(g0, g1, g2);
    k_work<<<1200, 256>>>(img, seg, vf0, vf1, vf2);
    k_attout<<<HW / 256, 256>>>(img, seg, sbb, (float*)d_out);
}

// round 11
// speedup vs baseline: 1.0541x; 1.0541x over previous
#include <cuda_runtime.h>
#include <math.h>

#define Hh 160
#define Ww 480
#define HW 76800
#define NP 120000

// ---------------- scratch (no allocations allowed) ----------------
__device__ __align__(16) int    d_win[3][HW];
__device__ __align__(16) float4 d_G0[9][16];    // folded red_w0 -> tap weights [k][c/4]
__device__ __align__(16) float4 d_G1[9][32];    // folded red_w1 -> tap weights
__device__ __align__(16) float4 d_Wpt[9][64];   // sb_w[256:512] transposed to [k][o/4]
__device__ __align__(16) float4 d_Wb[768];      // img tap weights, [c][12] padded rows
__device__ float  d_cb[9];                      // folded bias constants per tap
__device__ __align__(16) float  d_ti[9][HW];    // image-part tap maps (incl cb)
__device__ __align__(16) float  d_tp[9][HW];    // voxel tap maps (REDG-accumulated)

// ---------------- K0: prep (blocks 0..8) + init (blocks 9..683) --------------
__global__ void k_initprep(const float* __restrict__ rw0, const float* __restrict__ rb0,
                           const float* __restrict__ rw1, const float* __restrict__ rb1,
                           const float* __restrict__ sbw) {
    int b = blockIdx.x;
    int tid = threadIdx.x;
    if (b < 9) {
        int k = b;
        ((float*)d_Wb)[tid * 12 + k] = sbw[tid * 9 + k];           // img weights, padded rows
        ((float*)d_Wpt)[k * 256 + tid] = sbw[(256 + tid) * 9 + k];
        if (tid < 64) {
            float s = 0.f;
            for (int o = 0; o < 256; o++) s += rw0[o * 64 + tid] * sbw[(256 + o) * 9 + k];
            ((float*)d_G0)[k * 64 + tid] = s;
        }
        if (tid < 128) {
            float s = 0.f;
            for (int o = 0; o < 256; o++) s += rw1[o * 128 + tid] * sbw[(256 + o) * 9 + k];
            ((float*)d_G1)[k * 128 + tid] = s;
        }
        if (tid == 0) {
            float s = 0.f;
            for (int o = 0; o < 256; o++) s += (rb0[o] + rb1[o]) * sbw[(256 + o) * 9 + k];
            d_cb[k] = s;
        }
    } else {
        int i = (b - 9) * 256 + tid;          // 0 .. 172799 float4 over d_tp
        ((float4*)d_tp)[i] = make_float4(0.f, 0.f, 0.f, 0.f);
        if (i < 3 * HW / 4) ((int4*)d_win)[i] = make_int4(-1, -1, -1, -1);
    }
}

// ---------------- K1: scatter, last-write-wins == max point index ------------
__global__ void k_scatter(const int* __restrict__ g0, const int* __restrict__ g1,
                          const int* __restrict__ g2) {
    int i = blockIdx.x * blockDim.x + threadIdx.x;
    if (i >= 3 * NP) return;
    int lvl = i / NP;
    int p = i - lvl * NP;
    const int* g = (lvl == 0) ? g0 : ((lvl == 1) ? g1 : g2);
    int2 xy = ((const int2*)g)[p];
    if (xy.x >= 0 && xy.x < Ww && xy.y >= 0 && xy.y < Hh)
        atomicMax(&d_win[lvl][xy.y * Ww + xy.x], p);
}

// ---------------- img part: quad-major float4 loads (R7 scalar form) ---------
// warp = 8 quad-slots x 4 channel-lanes; lane loads float4 (4 px) per channel
__device__ __forceinline__ void img_body(const float* __restrict__ img,
                                         const float* __restrict__ seg,
                                         float* sWf, int blk) {
    int tid = threadIdx.x;
    for (int i = tid; i < 768; i += 256) ((float4*)sWf)[i] = d_Wb[i];
    __shared__ float scb[9];
    if (tid < 9) scb[tid] = d_cb[tid];
    __syncthreads();

    int lane = tid & 31;
    int w    = tid >> 5;
    int cs   = lane & 3;    // channel lane (0..3)
    int sub  = lane >> 2;   // quad slot (0..7)
    int px   = blk * 256 + w * 32 + sub * 4;

    float4 acc[9];
#pragma unroll
    for (int k = 0; k < 9; k++) acc[k] = make_float4(0.f, 0.f, 0.f, 0.f);

    for (int m = 0; m < 64; m++) {
        int c = cs + 4 * m;
        float4 v = *(const float4*)(img + (size_t)c * HW + px);
        const float* wp = sWf + c * 12;
        float4 w0 = *(const float4*)wp;
        float4 w1 = *(const float4*)(wp + 4);
        float  w8 = wp[8];
        acc[0].x += v.x * w0.x; acc[0].y += v.y * w0.x; acc[0].z += v.z * w0.x; acc[0].w += v.w * w0.x;
        acc[1].x += v.x * w0.y; acc[1].y += v.y * w0.y; acc[1].z += v.z * w0.y; acc[1].w += v.w * w0.y;
        acc[2].x += v.x * w0.z; acc[2].y += v.y * w0.z; acc[2].z += v.z * w0.z; acc[2].w += v.w * w0.z;
        acc[3].x += v.x * w0.w; acc[3].y += v.y * w0.w; acc[3].z += v.z * w0.w; acc[3].w += v.w * w0.w;
        acc[4].x += v.x * w1.x; acc[4].y += v.y * w1.x; acc[4].z += v.z * w1.x; acc[4].w += v.w * w1.x;
        acc[5].x += v.x * w1.y; acc[5].y += v.y * w1.y; acc[5].z += v.z * w1.y; acc[5].w += v.w * w1.y;
        acc[6].x += v.x * w1.z; acc[6].y += v.y * w1.z; acc[6].z += v.z * w1.z; acc[6].w += v.w * w1.z;
        acc[7].x += v.x * w1.w; acc[7].y += v.y * w1.w; acc[7].z += v.z * w1.w; acc[7].w += v.w * w1.w;
        acc[8].x += v.x * w8;   acc[8].y += v.y * w8;   acc[8].z += v.z * w8;   acc[8].w += v.w * w8;
    }

    // reduce across the 4 channel-lanes (xor 1, 2)
#pragma unroll
    for (int k = 0; k < 9; k++) {
        acc[k].x += __shfl_xor_sync(0xffffffffu, acc[k].x, 1);
        acc[k].y += __shfl_xor_sync(0xffffffffu, acc[k].y, 1);
        acc[k].z += __shfl_xor_sync(0xffffffffu, acc[k].z, 1);
        acc[k].w += __shfl_xor_sync(0xffffffffu, acc[k].w, 1);
        acc[k].x += __shfl_xor_sync(0xffffffffu, acc[k].x, 2);
        acc[k].y += __shfl_xor_sync(0xffffffffu, acc[k].y, 2);
        acc[k].z += __shfl_xor_sync(0xffffffffu, acc[k].z, 2);
        acc[k].w += __shfl_xor_sync(0xffffffffu, acc[k].w, 2);
    }
    if (cs == 0) {
        float4 sg = *(const float4*)(seg + HW + px);
#pragma unroll
        for (int k = 0; k < 9; k++) {
            float4 o;
            o.x = scb[k] + sg.x * acc[k].x;
            o.y = scb[k] + sg.y * acc[k].y;
            o.z = scb[k] + sg.z * acc[k].z;
            o.w = scb[k] + sg.w * acc[k].w;
            *(float4*)(&d_ti[k][px]) = o;
        }
    }
}

// ---------------- voxel part: in-smem compaction + gather + REDG (R8 form) ---
template <int LVL, int C4>
__device__ __forceinline__ void voxel_body(const float* __restrict__ vf,
                                           float4* sw, int2* s_lst, int* s_w,
                                           int blk) {
    int tid = threadIdx.x;
    const float4* wsrc = (LVL == 0) ? (const float4*)d_G0
                        : (LVL == 1) ? (const float4*)d_G1
                                     : (const float4*)d_Wpt;
    for (int i = tid; i < 9 * C4; i += 256) sw[i] = wsrc[i];

    // local compaction of this block's 256 cells
    int cell = blk * 256 + tid;
    int p = d_win[LVL][cell];
    bool v = p >= 0;
    unsigned m = __ballot_sync(0xffffffffu, v);
    int lane = tid & 31;
    int w    = tid >> 5;
    if (lane == 0) s_w[w] = __popc(m);
    __syncthreads();
    if (tid == 0) {
        int t = 0;
#pragma unroll
        for (int i = 0; i < 8; i++) { int c = s_w[i]; s_w[i] = t; t += c; }
        s_w[8] = t;
    }
    __syncthreads();
    if (v) {
        int pos = s_w[w] + __popc(m & ((1u << lane) - 1));
        s_lst[pos] = make_int2(cell, p);
    }
    __syncthreads();
    int n = s_w[8];

    int sub = lane >> 3;   // slot within warp (0..3)
    int cs  = lane & 7;    // channel lane (0..7)

    for (int base = 0; base < n; base += 64) {
        int i0 = base + w * 8 + sub * 2;
        int i1 = i0 + 1;
        bool ok0 = i0 < n;
        bool ok1 = i1 < n;
        int2 e0 = ok0 ? s_lst[i0] : make_int2(0, 0);
        int2 e1 = ok1 ? s_lst[i1] : make_int2(0, 0);
        const float4* rowA = (const float4*)vf + (size_t)e0.y * C4;
        const float4* rowB = (const float4*)vf + (size_t)e1.y * C4;

        float accA[9], accB[9];
#pragma unroll
        for (int k = 0; k < 9; k++) { accA[k] = 0.f; accB[k] = 0.f; }

#pragma unroll 2
        for (int mm = 0; mm < C4 / 8; mm++) {
            int c4 = cs + 8 * mm;
            float4 va = rowA[c4];
            float4 vb = rowB[c4];
#pragma unroll
            for (int k = 0; k < 9; k++) {
                float4 wv = sw[k * C4 + c4];
                accA[k] += va.x * wv.x + va.y * wv.y + va.z * wv.z + va.w * wv.w;
                accB[k] += vb.x * wv.x + vb.y * wv.y + vb.z * wv.z + vb.w * wv.w;
            }
        }
#pragma unroll
        for (int k = 0; k < 9; k++) {
            float sA = accA[k];
            float sB = accB[k];
            sA += __shfl_xor_sync(0xffffffffu, sA, 1);
            sB += __shfl_xor_sync(0xffffffffu, sB, 1);
            sA += __shfl_xor_sync(0xffffffffu, sA, 2);
            sB += __shfl_xor_sync(0xffffffffu, sB, 2);
            sA += __shfl_xor_sync(0xffffffffu, sA, 4);
            sB += __shfl_xor_sync(0xffffffffu, sB, 4);
            if (cs == 0) {
                if (ok0) atomicAdd(&d_tp[k][e0.x], sA);   // REDG.F32, no return
                if (ok1) atomicAdd(&d_tp[k][e1.x], sB);
            }
        }
    }
}

// ---------------- K2: merged work kernel, interleaved block types -------------
// 1200 blocks: b&3 -> {lvl2, lvl1, lvl0, img}, each 300 blocks of 256 cells/px
__global__ void __launch_bounds__(256, 4) k_work(const float* __restrict__ img,
                                                 const float* __restrict__ seg,
                                                 const float* __restrict__ vf0,
                                                 const float* __restrict__ vf1,
                                                 const float* __restrict__ vf2) {
    __shared__ __align__(16) float swf[3072];   // 12KB weight buffer
    __shared__ __align__(16) int2 s_lst[256];
    __shared__ int s_w[9];
    int b = blockIdx.x;
    int type = b & 3;
    int sb = b >> 2;
    if (type == 0)      voxel_body<2, 64>(vf2, (float4*)swf, s_lst, s_w, sb);
    else if (type == 1) voxel_body<1, 32>(vf1, (float4*)swf, s_lst, s_w, sb);
    else if (type == 2) voxel_body<0, 16>(vf0, (float4*)swf, s_lst, s_w, sb);
    else                img_body(img, seg, swf, sb);
}

// ---------------- K3: att (128 px into smem) + gated output stream ------------
// 600 blocks x 128 px: phase A computes att (threads 0..127), phase B streams
__global__ void __launch_bounds__(256) k_attout(const float* __restrict__ img,
                                                const float* __restrict__ seg,
                                                const float* __restrict__ sbb,
                                                float* __restrict__ out) {
    __shared__ __align__(16) float satt[128];
    int tid = threadIdx.x;
    int base = blockIdx.x * 128;
    if (tid < 128) {
        int pix = base + tid;
        int y = pix / Ww;
        int x = pix - y * Ww;
        float sum = sbb[0];
#pragma unroll
        for (int ky = 0; ky < 3; ky++) {
            int yy = y + ky - 1;
            if (yy < 0 || yy >= Hh) continue;
#pragma unroll
            for (int kx = 0; kx < 3; kx++) {
                int xx = x + kx - 1;
                if (xx < 0 || xx >= Ww) continue;
                int kk = ky * 3 + kx;
                int ni = yy * Ww + xx;
                sum += d_ti[kk][ni] + d_tp[kk][ni];
            }
        }
        float att = 1.f / (1.f + expf(-sum));
        satt[tid] = att * seg[HW + pix];
    }
    __syncthreads();

    // stream all 256 channels for this block's 128 pixels (32 float4 per channel)
    int q = tid & 31;          // pixel-quad within block (0..31)
    int c0 = tid >> 5;         // starting channel (0..7)
    float4 a = ((const float4*)satt)[q];
    const float4* im4 = (const float4*)img;
    float4* o4 = (float4*)out;
    size_t idx = (size_t)c0 * (HW / 4) + (base / 4) + q;
#pragma unroll 8
    for (int c = c0; c < 256; c += 8, idx += (size_t)8 * (HW / 4)) {
        float4 v = im4[idx];
        v.x *= a.x; v.y *= a.y; v.z *= a.z; v.w *= a.w;
        o4[idx] = v;
    }
}

extern "C" void kernel_launch(void* const* d_in, const int* in_sizes, int n_in,
                              void* d_out, int out_size) {
    const float* img = (const float*)d_in[0];
    const float* seg = (const float*)d_in[1];

    int iv0, iv1, iv2, ig0, ig1, ig2;
    if (in_sizes[3] == 2 * NP) { iv0 = 2; ig0 = 3; iv1 = 4; ig1 = 5; iv2 = 6; ig2 = 7; }
    else                       { iv0 = 2; iv1 = 3; iv2 = 4; ig0 = 5; ig1 = 6; ig2 = 7; }

    const float* vf0 = (const float*)d_in[iv0];
    const float* vf1 = (const float*)d_in[iv1];
    const float* vf2 = (const float*)d_in[iv2];
    const int*   g0  = (const int*)d_in[ig0];
    const int*   g1  = (const int*)d_in[ig1];
    const int*   g2  = (const int*)d_in[ig2];
    const float* rw0 = (const float*)d_in[8];
    const float* rb0 = (const float*)d_in[9];
    const float* rw1 = (const float*)d_in[10];
    const float* rb1 = (const float*)d_in[11];
    const float* sbw = (const float*)d_in[12];
    const float* sbb = (const float*)d_in[13];

    k_initprep<<<684, 256>>>(rw0, rb0, rw1, rb1, sbw);
    k_scatter<<<(3 * NP + 255) / 256, 256>>>(g0, g1, g2);
    k_work<<<1200, 256>>>(img, seg, vf0, vf1, vf2);
    k_attout<<<HW / 128, 256>>>(img, seg, sbb, (float*)d_out);
}